// round 9
// baseline (speedup 1.0000x reference)
#include <cuda_runtime.h>
#include <math.h>

#define N_NODES 50000
#define N_EDGES 600000
#define N_RELS  500
#define DIM     128
#define NODE_BLOCKS ((N_NODES + 63) / 64)   // 782
#define REL_BLOCKS  ((N_RELS + 63) / 64)    // 8
#define SCAN_CHUNKS ((N_NODES + 1023) / 1024)   // 49

// ---- scratch (no allocations allowed) ----
__device__ __align__(16) float g_m_node[N_NODES * DIM];
__device__ __align__(16) float g_m_rel[N_RELS * DIM];
__device__ float g_s_src[N_NODES];
__device__ float g_s_tgt[N_NODES];
__device__ float g_s_rel[N_RELS];
__device__ float g_dummy[N_RELS];
__device__ int   g_count[N_NODES];       // zero-init; re-zeroed by k_scan_add each run
__device__ int   g_offset[N_NODES + 1];
__device__ int   g_cursor[N_NODES];
__device__ int   g_blocksum[SCAN_CHUNKS];
__device__ __align__(8) uint2 g_epack[N_EDGES];   // {src | rel<<16, exp(score) bits}

// ---------------------------------------------------------------------------
__device__ __forceinline__ unsigned long long fma2(unsigned long long a,
                                                   unsigned long long b,
                                                   unsigned long long c) {
    unsigned long long d;
    asm("fma.rn.f32x2 %0, %1, %2, %3;" : "=l"(d) : "l"(a), "l"(b), "l"(c));
    return d;
}
__device__ __forceinline__ unsigned long long add2(unsigned long long a,
                                                   unsigned long long b) {
    unsigned long long d;
    asm("add.rn.f32x2 %0, %1, %2;" : "=l"(d) : "l"(a), "l"(b));
    return d;
}
__device__ __forceinline__ unsigned long long pack2(float x) {
    unsigned long long d;
    asm("mov.b64 %0, {%1, %1};" : "=l"(d) : "r"(__float_as_uint(x)));
    return d;
}
union F4U { float4 f4; unsigned long long u[2]; };

// ---------------------------------------------------------------------------
// Merged row transform for nodes AND rels in one launch.
// Blocks [0, NODE_BLOCKS): nodes;  [NODE_BLOCKS, ..): rels.
// m = x @ W^T + b ; s1 = x.v1 ; s2 = x.v2. W^T in smem, f32x2 FFMA,
// dst histogram fused (fire-and-forget atomics).
__global__ void k_precomp(const float* __restrict__ Xn, const float* __restrict__ Xr,
                          const float* __restrict__ Wn, const float* __restrict__ bn,
                          const float* __restrict__ Wr, const float* __restrict__ br,
                          const float* __restrict__ attn_w,
                          const int4* __restrict__ dst4) {
    extern __shared__ float sm[];
    float* Wt  = sm;                    // 128*132
    float* xs  = Wt + DIM * 132;        // 64*128
    float* sv1 = xs + 64 * DIM;         // 128
    float* sv2 = sv1 + DIM;             // 128

    int tid = threadIdx.x;
    int blk = blockIdx.x;
    int mode = (blk >= NODE_BLOCKS);

    const float* X  = mode ? Xr : Xn;
    const float* W  = mode ? Wr : Wn;
    const float* b  = mode ? br : bn;
    const float* v1 = mode ? attn_w + 2 * DIM : attn_w;
    const float* v2 = mode ? attn_w + 2 * DIM : attn_w + DIM;
    float* out_m  = mode ? g_m_rel : g_m_node;
    float* out_s1 = mode ? g_s_rel : g_s_src;
    float* out_s2 = mode ? g_dummy : g_s_tgt;
    int n_rows    = mode ? N_RELS  : N_NODES;
    int base      = (mode ? (blk - NODE_BLOCKS) : blk) * 64;

    // fused histogram over all blocks
    for (int i = blk * blockDim.x + tid; i < N_EDGES / 4; i += gridDim.x * blockDim.x) {
        int4 d = dst4[i];
        atomicAdd(&g_count[d.x], 1);
        atomicAdd(&g_count[d.y], 1);
        atomicAdd(&g_count[d.z], 1);
        atomicAdd(&g_count[d.w], 1);
    }

    for (int idx = tid; idx < DIM * DIM; idx += blockDim.x) {
        int j = idx >> 7, k = idx & 127;
        Wt[k * 132 + j] = W[idx];
    }
    for (int k = tid; k < DIM; k += blockDim.x) { sv1[k] = v1[k]; sv2[k] = v2[k]; }

    for (int idx = tid; idx < 64 * (DIM / 4); idx += blockDim.x) {
        int n = idx >> 5, c = idx & 31;
        int row = base + n;
        float4 v = make_float4(0.f, 0.f, 0.f, 0.f);
        if (row < n_rows) v = ((const float4*)X)[row * (DIM / 4) + c];
        ((float4*)xs)[n * (DIM / 4) + c] = v;
    }
    __syncthreads();

    int warp = tid >> 5, lane = tid & 31;
    F4U bu; bu.f4 = ((const float4*)b)[lane];

    unsigned long long alo[8], ahi[8];
#pragma unroll
    for (int i = 0; i < 8; i++) { alo[i] = bu.u[0]; ahi[i] = bu.u[1]; }

    int n0 = warp * 8;
    const float4* xr4 = (const float4*)(xs + n0 * DIM);   // row stride 32 float4
    const float4* Wt4 = (const float4*)Wt;                // row stride 33 float4

#pragma unroll 2
    for (int k4 = 0; k4 < DIM / 4; k4++) {
        float4 xv[8];
#pragma unroll
        for (int i = 0; i < 8; i++) xv[i] = xr4[i * 32 + k4];
#pragma unroll
        for (int q = 0; q < 4; q++) {
            int k = k4 * 4 + q;
            F4U w; w.f4 = Wt4[k * 33 + lane];
#pragma unroll
            for (int i = 0; i < 8; i++) {
                float xc = (q == 0) ? xv[i].x : (q == 1) ? xv[i].y
                         : (q == 2) ? xv[i].z : xv[i].w;
                unsigned long long xx = pack2(xc);
                alo[i] = fma2(w.u[0], xx, alo[i]);
                ahi[i] = fma2(w.u[1], xx, ahi[i]);
            }
        }
    }

    const float* xr0 = xs + n0 * DIM;
#pragma unroll
    for (int i = 0; i < 8; i++) {
        int row = base + n0 + i;
        if (row >= n_rows) break;
        F4U o; o.u[0] = alo[i]; o.u[1] = ahi[i];
        ((float4*)out_m)[row * (DIM / 4) + lane] = o.f4;
        const float* xr = xr0 + i * DIM;
        float p1 = 0.f, p2 = 0.f;
#pragma unroll
        for (int q = 0; q < 4; q++) {
            int k = lane * 4 + q;
            float xv = xr[k];
            p1 += xv * sv1[k];
            p2 += xv * sv2[k];
        }
#pragma unroll
        for (int o2 = 16; o2; o2 >>= 1) {
            p1 += __shfl_down_sync(0xffffffffu, p1, o2);
            p2 += __shfl_down_sync(0xffffffffu, p2, o2);
        }
        if (lane == 0) { out_s1[row] = p1; out_s2[row] = p2; }
    }
}

// ---------------------------------------------------------------------------
// Coalesced two-kernel scan.
__global__ void k_scan_local() {
    __shared__ int s[1024];
    int tid = threadIdx.x;
    int idx = blockIdx.x * 1024 + tid;
    int v = (idx < N_NODES) ? g_count[idx] : 0;
    s[tid] = v;
    __syncthreads();
#pragma unroll
    for (int off = 1; off < 1024; off <<= 1) {
        int t = (tid >= off) ? s[tid - off] : 0;
        __syncthreads();
        s[tid] += t;
        __syncthreads();
    }
    if (idx < N_NODES) g_offset[idx] = s[tid] - v;   // exclusive within chunk
    if (tid == 1023) g_blocksum[blockIdx.x] = s[tid];
}

__global__ void k_scan_add() {
    __shared__ int s_carry;
    int tid = threadIdx.x;
    int blk = blockIdx.x;
    int chunk = (blk * 256) >> 10;      // 256 nodes per block, all in one chunk

    if (tid < 32) {
        int v = 0;
        if (tid < chunk) v += g_blocksum[tid];
        if (tid + 32 < chunk) v += g_blocksum[tid + 32];
#pragma unroll
        for (int o = 16; o; o >>= 1) v += __shfl_xor_sync(0xffffffffu, v, o);
        if (tid == 0) s_carry = v;
    }
    __syncthreads();
    int carry = s_carry;

    int idx = blk * 256 + tid;
    if (idx < N_NODES) {
        int v = g_offset[idx] + carry;
        g_offset[idx] = v;
        g_cursor[idx] = v;
        g_count[idx]  = 0;   // restore invariant for next execution
    }
    if (idx == 0) g_offset[N_NODES] = N_EDGES;
}

// ---------------------------------------------------------------------------
// Fill CSR with (pack, exp(score)) — exp computed here, off agg's critical path.
__global__ void k_fill(const int4* __restrict__ src4, const int4* __restrict__ dst4,
                       const int4* __restrict__ rel4, const float* __restrict__ attn_b) {
    int i = blockIdx.x * blockDim.x + threadIdx.x;
    if (i >= N_EDGES / 4) return;
    int4 s = src4[i];
    int4 d = dst4[i];
    int4 r = rel4[i];
    float ab = attn_b[0];

    float e0 = __expf(g_s_src[s.x] + g_s_rel[r.x] + g_s_tgt[d.x] + ab);
    float e1 = __expf(g_s_src[s.y] + g_s_rel[r.y] + g_s_tgt[d.y] + ab);
    float e2 = __expf(g_s_src[s.z] + g_s_rel[r.z] + g_s_tgt[d.z] + ab);
    float e3 = __expf(g_s_src[s.w] + g_s_rel[r.w] + g_s_tgt[d.w] + ab);

    int p0 = atomicAdd(&g_cursor[d.x], 1);
    int p1 = atomicAdd(&g_cursor[d.y], 1);
    int p2 = atomicAdd(&g_cursor[d.z], 1);
    int p3 = atomicAdd(&g_cursor[d.w], 1);
    g_epack[p0] = make_uint2((unsigned)s.x | ((unsigned)r.x << 16), __float_as_uint(e0));
    g_epack[p1] = make_uint2((unsigned)s.y | ((unsigned)r.y << 16), __float_as_uint(e1));
    g_epack[p2] = make_uint2((unsigned)s.z | ((unsigned)r.z << 16), __float_as_uint(e2));
    g_epack[p3] = make_uint2((unsigned)s.w | ((unsigned)r.w << 16), __float_as_uint(e3));
}

// ---------------------------------------------------------------------------
// One warp per dst node: weighted aggregate with precomputed exp.
// f32x2 packed accumulation: 2 ADD + 2 FMA per edge instead of 12 scalar ops.
__global__ void k_node_agg(const float* __restrict__ node_emb,
                           float* __restrict__ out) {
    int gid = blockIdx.x * blockDim.x + threadIdx.x;
    int n = gid >> 5;
    if (n >= N_NODES) return;
    int lane = gid & 31;
    int beg = g_offset[n], end = g_offset[n + 1];
    float4 res;
    if (end > beg) {
        unsigned long long acc0 = 0ull, acc1 = 0ull;   // {0.f,0.f} packed
        float denom = 0.f;
#pragma unroll 2
        for (int e = beg; e < end; e++) {
            uint2 pe = g_epack[e];
            float ex = __uint_as_float(pe.y);
            int s = pe.x & 0xFFFF;
            int r = pe.x >> 16;
            F4U mv; mv.f4 = ((const float4*)g_m_node)[s * (DIM / 4) + lane];
            F4U rv; rv.f4 = ((const float4*)g_m_rel)[r * (DIM / 4) + lane];
            unsigned long long ex2 = pack2(ex);
            acc0 = fma2(add2(mv.u[0], rv.u[0]), ex2, acc0);
            acc1 = fma2(add2(mv.u[1], rv.u[1]), ex2, acc1);
            denom += ex;
        }
        float inv = 1.f / denom;
        F4U a; a.u[0] = acc0; a.u[1] = acc1;
        res = make_float4(a.f4.x * inv, a.f4.y * inv, a.f4.z * inv, a.f4.w * inv);
    } else {
        res = ((const float4*)node_emb)[n * (DIM / 4) + lane];
    }
    ((float4*)out)[n * (DIM / 4) + lane] = res;
}

// ---------------------------------------------------------------------------
extern "C" void kernel_launch(void* const* d_in, const int* in_sizes, int n_in,
                              void* d_out, int out_size) {
    const float* node_emb = (const float*)d_in[0];
    const float* rel_emb  = (const float*)d_in[1];
    const float* Wn       = (const float*)d_in[2];
    const float* bn       = (const float*)d_in[3];
    const float* Wr       = (const float*)d_in[4];
    const float* br       = (const float*)d_in[5];
    const float* attn_w   = (const float*)d_in[6];
    const float* attn_b   = (const float*)d_in[7];
    const int*   src      = (const int*)d_in[8];
    const int*   dst      = (const int*)d_in[9];
    const int*   rel      = (const int*)d_in[10];
    float* out = (float*)d_out;

    const int SMEM = (DIM * 132 + 64 * DIM + 2 * DIM) * (int)sizeof(float);  // 101,376 B
    cudaFuncSetAttribute(k_precomp, cudaFuncAttributeMaxDynamicSharedMemorySize, SMEM);

    int eb4 = (N_EDGES / 4 + 255) / 256;

    k_precomp<<<NODE_BLOCKS + REL_BLOCKS, 256, SMEM>>>(node_emb, rel_emb, Wn, bn,
                                                       Wr, br, attn_w,
                                                       (const int4*)dst);
    k_scan_local<<<SCAN_CHUNKS, 1024>>>();
    k_scan_add<<<(N_NODES + 255) / 256, 256>>>();
    k_fill<<<eb4, 256>>>((const int4*)src, (const int4*)dst, (const int4*)rel, attn_b);
    k_node_agg<<<(N_NODES * 32 + 255) / 256, 256>>>(node_emb, out);
}

// round 10
// speedup vs baseline: 1.0176x; 1.0176x over previous
#include <cuda_runtime.h>
#include <math.h>

#define N_NODES 50000
#define N_EDGES 600000
#define N_RELS  500
#define DIM     128
#define NODE_BLOCKS ((N_NODES + 63) / 64)   // 782
#define REL_BLOCKS  ((N_RELS + 63) / 64)    // 8
#define SCAN_CHUNKS ((N_NODES + 255) / 256)   // 196

// ---- scratch (no allocations allowed) ----
__device__ __align__(16) float g_m_node[N_NODES * DIM];
__device__ __align__(16) float g_m_rel[N_RELS * DIM];
__device__ float g_s_src[N_NODES];
__device__ float g_s_tgt[N_NODES];
__device__ float g_s_rel[N_RELS];
__device__ float g_dummy[N_RELS];
__device__ int   g_count[N_NODES];       // zero-init; re-zeroed by k_scan_add each run
__device__ int   g_offset[N_NODES + 1];
__device__ int   g_cursor[N_NODES];
__device__ int   g_blocksum[SCAN_CHUNKS];
__device__ __align__(8) uint2 g_epack[N_EDGES];   // {src | rel<<16, exp(score) bits}

// ---------------------------------------------------------------------------
__device__ __forceinline__ unsigned long long fma2(unsigned long long a,
                                                   unsigned long long b,
                                                   unsigned long long c) {
    unsigned long long d;
    asm("fma.rn.f32x2 %0, %1, %2, %3;" : "=l"(d) : "l"(a), "l"(b), "l"(c));
    return d;
}
__device__ __forceinline__ unsigned long long pack2(float x) {
    unsigned long long d;
    asm("mov.b64 %0, {%1, %1};" : "=l"(d) : "r"(__float_as_uint(x)));
    return d;
}
union F4U { float4 f4; unsigned long long u[2]; };

// ---------------------------------------------------------------------------
// Merged row transform for nodes AND rels in one launch.
// Blocks [0, NODE_BLOCKS): nodes;  [NODE_BLOCKS, ..): rels.
// m = x @ W^T + b ; s1 = x.v1 ; s2 = x.v2. W^T in smem, f32x2 FFMA,
// dst histogram fused (fire-and-forget atomics).
__global__ void k_precomp(const float* __restrict__ Xn, const float* __restrict__ Xr,
                          const float* __restrict__ Wn, const float* __restrict__ bn,
                          const float* __restrict__ Wr, const float* __restrict__ br,
                          const float* __restrict__ attn_w,
                          const int4* __restrict__ dst4) {
    extern __shared__ float sm[];
    float* Wt  = sm;                    // 128*132
    float* xs  = Wt + DIM * 132;        // 64*128
    float* sv1 = xs + 64 * DIM;         // 128
    float* sv2 = sv1 + DIM;             // 128

    int tid = threadIdx.x;
    int blk = blockIdx.x;
    int mode = (blk >= NODE_BLOCKS);

    const float* X  = mode ? Xr : Xn;
    const float* W  = mode ? Wr : Wn;
    const float* b  = mode ? br : bn;
    const float* v1 = mode ? attn_w + 2 * DIM : attn_w;
    const float* v2 = mode ? attn_w + 2 * DIM : attn_w + DIM;
    float* out_m  = mode ? g_m_rel : g_m_node;
    float* out_s1 = mode ? g_s_rel : g_s_src;
    float* out_s2 = mode ? g_dummy : g_s_tgt;
    int n_rows    = mode ? N_RELS  : N_NODES;
    int base      = (mode ? (blk - NODE_BLOCKS) : blk) * 64;

    // fused histogram over all blocks
    for (int i = blk * blockDim.x + tid; i < N_EDGES / 4; i += gridDim.x * blockDim.x) {
        int4 d = dst4[i];
        atomicAdd(&g_count[d.x], 1);
        atomicAdd(&g_count[d.y], 1);
        atomicAdd(&g_count[d.z], 1);
        atomicAdd(&g_count[d.w], 1);
    }

    for (int idx = tid; idx < DIM * DIM; idx += blockDim.x) {
        int j = idx >> 7, k = idx & 127;
        Wt[k * 132 + j] = W[idx];
    }
    for (int k = tid; k < DIM; k += blockDim.x) { sv1[k] = v1[k]; sv2[k] = v2[k]; }

    for (int idx = tid; idx < 64 * (DIM / 4); idx += blockDim.x) {
        int n = idx >> 5, c = idx & 31;
        int row = base + n;
        float4 v = make_float4(0.f, 0.f, 0.f, 0.f);
        if (row < n_rows) v = ((const float4*)X)[row * (DIM / 4) + c];
        ((float4*)xs)[n * (DIM / 4) + c] = v;
    }
    __syncthreads();

    int warp = tid >> 5, lane = tid & 31;
    F4U bu; bu.f4 = ((const float4*)b)[lane];

    unsigned long long alo[8], ahi[8];
#pragma unroll
    for (int i = 0; i < 8; i++) { alo[i] = bu.u[0]; ahi[i] = bu.u[1]; }

    int n0 = warp * 8;
    const float4* xr4 = (const float4*)(xs + n0 * DIM);   // row stride 32 float4
    const float4* Wt4 = (const float4*)Wt;                // row stride 33 float4

#pragma unroll 2
    for (int k4 = 0; k4 < DIM / 4; k4++) {
        float4 xv[8];
#pragma unroll
        for (int i = 0; i < 8; i++) xv[i] = xr4[i * 32 + k4];
#pragma unroll
        for (int q = 0; q < 4; q++) {
            int k = k4 * 4 + q;
            F4U w; w.f4 = Wt4[k * 33 + lane];
#pragma unroll
            for (int i = 0; i < 8; i++) {
                float xc = (q == 0) ? xv[i].x : (q == 1) ? xv[i].y
                         : (q == 2) ? xv[i].z : xv[i].w;
                unsigned long long xx = pack2(xc);
                alo[i] = fma2(w.u[0], xx, alo[i]);
                ahi[i] = fma2(w.u[1], xx, ahi[i]);
            }
        }
    }

    const float* xr0 = xs + n0 * DIM;
#pragma unroll
    for (int i = 0; i < 8; i++) {
        int row = base + n0 + i;
        if (row >= n_rows) break;
        F4U o; o.u[0] = alo[i]; o.u[1] = ahi[i];
        ((float4*)out_m)[row * (DIM / 4) + lane] = o.f4;
        const float* xr = xr0 + i * DIM;
        float p1 = 0.f, p2 = 0.f;
#pragma unroll
        for (int q = 0; q < 4; q++) {
            int k = lane * 4 + q;
            float xv = xr[k];
            p1 += xv * sv1[k];
            p2 += xv * sv2[k];
        }
#pragma unroll
        for (int o2 = 16; o2; o2 >>= 1) {
            p1 += __shfl_down_sync(0xffffffffu, p1, o2);
            p2 += __shfl_down_sync(0xffffffffu, p2, o2);
        }
        if (lane == 0) { out_s1[row] = p1; out_s2[row] = p2; }
    }
}

// ---------------------------------------------------------------------------
// Coalesced two-kernel scan, 256-node chunks (196 blocks).
__global__ void k_scan_local() {
    __shared__ int s[256];
    int tid = threadIdx.x;
    int idx = blockIdx.x * 256 + tid;
    int v = (idx < N_NODES) ? g_count[idx] : 0;
    s[tid] = v;
    __syncthreads();
#pragma unroll
    for (int off = 1; off < 256; off <<= 1) {
        int t = (tid >= off) ? s[tid - off] : 0;
        __syncthreads();
        s[tid] += t;
        __syncthreads();
    }
    if (idx < N_NODES) g_offset[idx] = s[tid] - v;   // exclusive within chunk
    if (tid == 255) g_blocksum[blockIdx.x] = s[tid];
}

__global__ void k_scan_add() {
    __shared__ int s_carry;
    int tid = threadIdx.x;
    int chunk = blockIdx.x;          // 256 nodes per block == chunk size

    if (tid < 32) {
        int v = 0;
        for (int c = tid; c < chunk; c += 32) v += g_blocksum[c];
#pragma unroll
        for (int o = 16; o; o >>= 1) v += __shfl_xor_sync(0xffffffffu, v, o);
        if (tid == 0) s_carry = v;
    }
    __syncthreads();
    int carry = s_carry;

    int idx = chunk * 256 + tid;
    if (idx < N_NODES) {
        int v = g_offset[idx] + carry;
        g_offset[idx] = v;
        g_cursor[idx] = v;
        g_count[idx]  = 0;   // restore invariant for next execution
    }
    if (idx == 0) g_offset[N_NODES] = N_EDGES;
}

// ---------------------------------------------------------------------------
// Fill CSR with (pack, exp(score)) — 2 edges/thread for higher warp count.
__global__ void k_fill(const int2* __restrict__ src2, const int2* __restrict__ dst2,
                       const int2* __restrict__ rel2, const float* __restrict__ attn_b) {
    int i = blockIdx.x * blockDim.x + threadIdx.x;
    if (i >= N_EDGES / 2) return;
    int2 s = src2[i];
    int2 d = dst2[i];
    int2 r = rel2[i];
    float ab = attn_b[0];

    float e0 = __expf(g_s_src[s.x] + g_s_rel[r.x] + g_s_tgt[d.x] + ab);
    float e1 = __expf(g_s_src[s.y] + g_s_rel[r.y] + g_s_tgt[d.y] + ab);

    int p0 = atomicAdd(&g_cursor[d.x], 1);
    int p1 = atomicAdd(&g_cursor[d.y], 1);
    g_epack[p0] = make_uint2((unsigned)s.x | ((unsigned)r.x << 16), __float_as_uint(e0));
    g_epack[p1] = make_uint2((unsigned)s.y | ((unsigned)r.y << 16), __float_as_uint(e1));
}

// ---------------------------------------------------------------------------
// One warp per dst node: weighted aggregate with precomputed exp.
// (R8-proven scalar form.)
__global__ void k_node_agg(const float* __restrict__ node_emb,
                           float* __restrict__ out) {
    int gid = blockIdx.x * blockDim.x + threadIdx.x;
    int n = gid >> 5;
    if (n >= N_NODES) return;
    int lane = gid & 31;
    int beg = g_offset[n], end = g_offset[n + 1];
    float4 res;
    if (end > beg) {
        float4 acc = make_float4(0.f, 0.f, 0.f, 0.f);
        float denom = 0.f;
        for (int e = beg; e < end; e++) {
            uint2 pe = g_epack[e];
            float ex = __uint_as_float(pe.y);
            int s = pe.x & 0xFFFF;
            int r = pe.x >> 16;
            float4 mv = ((const float4*)g_m_node)[s * (DIM / 4) + lane];
            float4 rv = ((const float4*)g_m_rel)[r * (DIM / 4) + lane];
            acc.x += ex * (mv.x + rv.x);
            acc.y += ex * (mv.y + rv.y);
            acc.z += ex * (mv.z + rv.z);
            acc.w += ex * (mv.w + rv.w);
            denom += ex;
        }
        float inv = 1.f / denom;
        res = make_float4(acc.x * inv, acc.y * inv, acc.z * inv, acc.w * inv);
    } else {
        res = ((const float4*)node_emb)[n * (DIM / 4) + lane];
    }
    ((float4*)out)[n * (DIM / 4) + lane] = res;
}

// ---------------------------------------------------------------------------
extern "C" void kernel_launch(void* const* d_in, const int* in_sizes, int n_in,
                              void* d_out, int out_size) {
    const float* node_emb = (const float*)d_in[0];
    const float* rel_emb  = (const float*)d_in[1];
    const float* Wn       = (const float*)d_in[2];
    const float* bn       = (const float*)d_in[3];
    const float* Wr       = (const float*)d_in[4];
    const float* br       = (const float*)d_in[5];
    const float* attn_w   = (const float*)d_in[6];
    const float* attn_b   = (const float*)d_in[7];
    const int*   src      = (const int*)d_in[8];
    const int*   dst      = (const int*)d_in[9];
    const int*   rel      = (const int*)d_in[10];
    float* out = (float*)d_out;

    const int SMEM = (DIM * 132 + 64 * DIM + 2 * DIM) * (int)sizeof(float);  // 101,376 B
    cudaFuncSetAttribute(k_precomp, cudaFuncAttributeMaxDynamicSharedMemorySize, SMEM);

    int eb2 = (N_EDGES / 2 + 255) / 256;

    k_precomp<<<NODE_BLOCKS + REL_BLOCKS, 256, SMEM>>>(node_emb, rel_emb, Wn, bn,
                                                       Wr, br, attn_w,
                                                       (const int4*)dst);
    k_scan_local<<<SCAN_CHUNKS, 256>>>();
    k_scan_add<<<SCAN_CHUNKS, 256>>>();
    k_fill<<<eb2, 256>>>((const int2*)src, (const int2*)dst, (const int2*)rel, attn_b);
    k_node_agg<<<(N_NODES * 32 + 255) / 256, 256>>>(node_emb, out);
}

// round 11
// speedup vs baseline: 1.0361x; 1.0182x over previous
#include <cuda_runtime.h>
#include <math.h>

#define N_NODES 50000
#define N_EDGES 600000
#define N_RELS  500
#define DIM     128
#define NODE_BLOCKS ((N_NODES + 63) / 64)   // 782
#define REL_BLOCKS  ((N_RELS + 63) / 64)    // 8
#define SCAN_CHUNKS ((N_NODES + 255) / 256)   // 196
#define SCAN_FLAG   (1ull << 63)

// ---- scratch (no allocations allowed) ----
__device__ __align__(16) float g_m_node[N_NODES * DIM];
__device__ __align__(16) float g_m_rel[N_RELS * DIM];
__device__ float g_s_src[N_NODES];
__device__ float g_s_tgt[N_NODES];
__device__ float g_s_rel[N_RELS];
__device__ float g_dummy[N_RELS];
__device__ int   g_count[N_NODES];       // zero-init; re-zeroed by k_scan each run
__device__ int   g_offset[N_NODES + 1];
__device__ int   g_cursor[N_NODES];
__device__ unsigned long long g_scan_ll[SCAN_CHUNKS];  // aggregate | FLAG; reset by k_precomp
__device__ __align__(8) uint2 g_epack[N_EDGES];   // {src | rel<<16, exp(score) bits}

// ---------------------------------------------------------------------------
__device__ __forceinline__ unsigned long long fma2(unsigned long long a,
                                                   unsigned long long b,
                                                   unsigned long long c) {
    unsigned long long d;
    asm("fma.rn.f32x2 %0, %1, %2, %3;" : "=l"(d) : "l"(a), "l"(b), "l"(c));
    return d;
}
__device__ __forceinline__ unsigned long long pack2(float x) {
    unsigned long long d;
    asm("mov.b64 %0, {%1, %1};" : "=l"(d) : "r"(__float_as_uint(x)));
    return d;
}
union F4U { float4 f4; unsigned long long u[2]; };

// ---------------------------------------------------------------------------
// Merged row transform for nodes AND rels in one launch.
// Blocks [0, NODE_BLOCKS): nodes;  [NODE_BLOCKS, ..): rels.
// m = x @ W^T + b ; s1 = x.v1 ; s2 = x.v2. W^T in smem, f32x2 FFMA,
// dst histogram fused. Block 0 also resets the scan flags for this run.
__global__ void k_precomp(const float* __restrict__ Xn, const float* __restrict__ Xr,
                          const float* __restrict__ Wn, const float* __restrict__ bn,
                          const float* __restrict__ Wr, const float* __restrict__ br,
                          const float* __restrict__ attn_w,
                          const int4* __restrict__ dst4) {
    extern __shared__ float sm[];
    float* Wt  = sm;                    // 128*132
    float* xs  = Wt + DIM * 132;        // 64*128
    float* sv1 = xs + 64 * DIM;         // 128
    float* sv2 = sv1 + DIM;             // 128

    int tid = threadIdx.x;
    int blk = blockIdx.x;
    int mode = (blk >= NODE_BLOCKS);

    // reset scan flags for this execution (196 < 256)
    if (blk == 0 && tid < SCAN_CHUNKS) g_scan_ll[tid] = 0ull;

    const float* X  = mode ? Xr : Xn;
    const float* W  = mode ? Wr : Wn;
    const float* b  = mode ? br : bn;
    const float* v1 = mode ? attn_w + 2 * DIM : attn_w;
    const float* v2 = mode ? attn_w + 2 * DIM : attn_w + DIM;
    float* out_m  = mode ? g_m_rel : g_m_node;
    float* out_s1 = mode ? g_s_rel : g_s_src;
    float* out_s2 = mode ? g_dummy : g_s_tgt;
    int n_rows    = mode ? N_RELS  : N_NODES;
    int base      = (mode ? (blk - NODE_BLOCKS) : blk) * 64;

    // fused histogram over all blocks
    for (int i = blk * blockDim.x + tid; i < N_EDGES / 4; i += gridDim.x * blockDim.x) {
        int4 d = dst4[i];
        atomicAdd(&g_count[d.x], 1);
        atomicAdd(&g_count[d.y], 1);
        atomicAdd(&g_count[d.z], 1);
        atomicAdd(&g_count[d.w], 1);
    }

    for (int idx = tid; idx < DIM * DIM; idx += blockDim.x) {
        int j = idx >> 7, k = idx & 127;
        Wt[k * 132 + j] = W[idx];
    }
    for (int k = tid; k < DIM; k += blockDim.x) { sv1[k] = v1[k]; sv2[k] = v2[k]; }

    for (int idx = tid; idx < 64 * (DIM / 4); idx += blockDim.x) {
        int n = idx >> 5, c = idx & 31;
        int row = base + n;
        float4 v = make_float4(0.f, 0.f, 0.f, 0.f);
        if (row < n_rows) v = ((const float4*)X)[row * (DIM / 4) + c];
        ((float4*)xs)[n * (DIM / 4) + c] = v;
    }
    __syncthreads();

    int warp = tid >> 5, lane = tid & 31;
    F4U bu; bu.f4 = ((const float4*)b)[lane];

    unsigned long long alo[8], ahi[8];
#pragma unroll
    for (int i = 0; i < 8; i++) { alo[i] = bu.u[0]; ahi[i] = bu.u[1]; }

    int n0 = warp * 8;
    const float4* xr4 = (const float4*)(xs + n0 * DIM);   // row stride 32 float4
    const float4* Wt4 = (const float4*)Wt;                // row stride 33 float4

#pragma unroll 2
    for (int k4 = 0; k4 < DIM / 4; k4++) {
        float4 xv[8];
#pragma unroll
        for (int i = 0; i < 8; i++) xv[i] = xr4[i * 32 + k4];
#pragma unroll
        for (int q = 0; q < 4; q++) {
            int k = k4 * 4 + q;
            F4U w; w.f4 = Wt4[k * 33 + lane];
#pragma unroll
            for (int i = 0; i < 8; i++) {
                float xc = (q == 0) ? xv[i].x : (q == 1) ? xv[i].y
                         : (q == 2) ? xv[i].z : xv[i].w;
                unsigned long long xx = pack2(xc);
                alo[i] = fma2(w.u[0], xx, alo[i]);
                ahi[i] = fma2(w.u[1], xx, ahi[i]);
            }
        }
    }

    const float* xr0 = xs + n0 * DIM;
#pragma unroll
    for (int i = 0; i < 8; i++) {
        int row = base + n0 + i;
        if (row >= n_rows) break;
        F4U o; o.u[0] = alo[i]; o.u[1] = ahi[i];
        ((float4*)out_m)[row * (DIM / 4) + lane] = o.f4;
        const float* xr = xr0 + i * DIM;
        float p1 = 0.f, p2 = 0.f;
#pragma unroll
        for (int q = 0; q < 4; q++) {
            int k = lane * 4 + q;
            float xv = xr[k];
            p1 += xv * sv1[k];
            p2 += xv * sv2[k];
        }
#pragma unroll
        for (int o2 = 16; o2; o2 >>= 1) {
            p1 += __shfl_down_sync(0xffffffffu, p1, o2);
            p2 += __shfl_down_sync(0xffffffffu, p2, o2);
        }
        if (lane == 0) { out_s1[row] = p1; out_s2[row] = p2; }
    }
}

// ---------------------------------------------------------------------------
// Single-kernel decoupled-lookback exclusive scan over g_count.
// Writes g_offset + g_cursor, re-zeros g_count, sets sentinel.
__global__ void k_scan() {
    __shared__ int s[256];
    __shared__ int s_carry;
    int tid = threadIdx.x;
    int b   = blockIdx.x;
    int idx = b * 256 + tid;

    int v = (idx < N_NODES) ? g_count[idx] : 0;
    s[tid] = v;
    __syncthreads();
#pragma unroll
    for (int off = 1; off < 256; off <<= 1) {
        int t = (tid >= off) ? s[tid - off] : 0;
        __syncthreads();
        s[tid] += t;
        __syncthreads();
    }
    int incl = s[tid];   // inclusive prefix within chunk

    // publish this chunk's aggregate (value+flag in one atomic word)
    if (tid == 255)
        atomicExch(&g_scan_ll[b], (unsigned long long)(unsigned)s[255] | SCAN_FLAG);

    // warp 0: 32-wide lookback over predecessor aggregates
    if (tid < 32) {
        int running = 0;
        int pos = b - 1 - tid;
        while (__any_sync(0xffffffffu, pos >= 0)) {
            if (pos >= 0) {
                unsigned long long got;
                do { got = atomicAdd(&g_scan_ll[pos], 0ull); } while (!(got & SCAN_FLAG));
                running += (int)(unsigned)(got & 0xFFFFFFFFull);
            }
            pos -= 32;
        }
#pragma unroll
        for (int o = 16; o; o >>= 1) running += __shfl_xor_sync(0xffffffffu, running, o);
        if (tid == 0) s_carry = running;
    }
    __syncthreads();
    int carry = s_carry;

    if (idx < N_NODES) {
        int o = carry + incl - v;   // global exclusive prefix
        g_offset[idx] = o;
        g_cursor[idx] = o;
        g_count[idx]  = 0;          // restore invariant for next execution
    }
    if (idx == 0) g_offset[N_NODES] = N_EDGES;
}

// ---------------------------------------------------------------------------
// Fill CSR with (pack, exp(score)) — exp computed here, off agg's critical path.
__global__ void k_fill(const int4* __restrict__ src4, const int4* __restrict__ dst4,
                       const int4* __restrict__ rel4, const float* __restrict__ attn_b) {
    int i = blockIdx.x * blockDim.x + threadIdx.x;
    if (i >= N_EDGES / 4) return;
    int4 s = src4[i];
    int4 d = dst4[i];
    int4 r = rel4[i];
    float ab = attn_b[0];

    float e0 = __expf(g_s_src[s.x] + g_s_rel[r.x] + g_s_tgt[d.x] + ab);
    float e1 = __expf(g_s_src[s.y] + g_s_rel[r.y] + g_s_tgt[d.y] + ab);
    float e2 = __expf(g_s_src[s.z] + g_s_rel[r.z] + g_s_tgt[d.z] + ab);
    float e3 = __expf(g_s_src[s.w] + g_s_rel[r.w] + g_s_tgt[d.w] + ab);

    int p0 = atomicAdd(&g_cursor[d.x], 1);
    int p1 = atomicAdd(&g_cursor[d.y], 1);
    int p2 = atomicAdd(&g_cursor[d.z], 1);
    int p3 = atomicAdd(&g_cursor[d.w], 1);
    g_epack[p0] = make_uint2((unsigned)s.x | ((unsigned)r.x << 16), __float_as_uint(e0));
    g_epack[p1] = make_uint2((unsigned)s.y | ((unsigned)r.y << 16), __float_as_uint(e1));
    g_epack[p2] = make_uint2((unsigned)s.z | ((unsigned)r.z << 16), __float_as_uint(e2));
    g_epack[p3] = make_uint2((unsigned)s.w | ((unsigned)r.w << 16), __float_as_uint(e3));
}

// ---------------------------------------------------------------------------
// One warp per dst node: weighted aggregate with precomputed exp.
__global__ void k_node_agg(const float* __restrict__ node_emb,
                           float* __restrict__ out) {
    int gid = blockIdx.x * blockDim.x + threadIdx.x;
    int n = gid >> 5;
    if (n >= N_NODES) return;
    int lane = gid & 31;
    int beg = g_offset[n], end = g_offset[n + 1];
    float4 res;
    if (end > beg) {
        float4 acc = make_float4(0.f, 0.f, 0.f, 0.f);
        float denom = 0.f;
        for (int e = beg; e < end; e++) {
            uint2 pe = g_epack[e];
            float ex = __uint_as_float(pe.y);
            int s = pe.x & 0xFFFF;
            int r = pe.x >> 16;
            float4 mv = ((const float4*)g_m_node)[s * (DIM / 4) + lane];
            float4 rv = ((const float4*)g_m_rel)[r * (DIM / 4) + lane];
            acc.x += ex * (mv.x + rv.x);
            acc.y += ex * (mv.y + rv.y);
            acc.z += ex * (mv.z + rv.z);
            acc.w += ex * (mv.w + rv.w);
            denom += ex;
        }
        float inv = 1.f / denom;
        res = make_float4(acc.x * inv, acc.y * inv, acc.z * inv, acc.w * inv);
    } else {
        res = ((const float4*)node_emb)[n * (DIM / 4) + lane];
    }
    ((float4*)out)[n * (DIM / 4) + lane] = res;
}

// ---------------------------------------------------------------------------
extern "C" void kernel_launch(void* const* d_in, const int* in_sizes, int n_in,
                              void* d_out, int out_size) {
    const float* node_emb = (const float*)d_in[0];
    const float* rel_emb  = (const float*)d_in[1];
    const float* Wn       = (const float*)d_in[2];
    const float* bn       = (const float*)d_in[3];
    const float* Wr       = (const float*)d_in[4];
    const float* br       = (const float*)d_in[5];
    const float* attn_w   = (const float*)d_in[6];
    const float* attn_b   = (const float*)d_in[7];
    const int*   src      = (const int*)d_in[8];
    const int*   dst      = (const int*)d_in[9];
    const int*   rel      = (const int*)d_in[10];
    float* out = (float*)d_out;

    const int SMEM = (DIM * 132 + 64 * DIM + 2 * DIM) * (int)sizeof(float);  // 101,376 B
    cudaFuncSetAttribute(k_precomp, cudaFuncAttributeMaxDynamicSharedMemorySize, SMEM);

    int eb4 = (N_EDGES / 4 + 255) / 256;

    k_precomp<<<NODE_BLOCKS + REL_BLOCKS, 256, SMEM>>>(node_emb, rel_emb, Wn, bn,
                                                       Wr, br, attn_w,
                                                       (const int4*)dst);
    k_scan<<<SCAN_CHUNKS, 256>>>();
    k_fill<<<eb4, 256>>>((const int4*)src, (const int4*)dst, (const int4*)rel, attn_b);
    k_node_agg<<<(N_NODES * 32 + 255) / 256, 256>>>(node_emb, out);
}